// round 10
// baseline (speedup 1.0000x reference)
#include <cuda_runtime.h>

typedef unsigned long long ull;

#define Bn 128
#define Tn 512
#define Dn 32
#define Nn 64

// scratch for cross-d reduction (no allocations allowed)
__device__ float g_mu[Bn * Dn];
__device__ float g_tb[Bn * Dn];

static __device__ __forceinline__ ull pack2(float lo, float hi) {
    ull r; asm("mov.b64 %0, {%1, %2};" : "=l"(r) : "f"(lo), "f"(hi)); return r;
}
static __device__ __forceinline__ void unpack2(ull v, float &lo, float &hi) {
    asm("mov.b64 {%0, %1}, %2;" : "=f"(lo), "=f"(hi) : "l"(v));
}
// packed 2xfp32 FMA (Blackwell): d = a*b + c
static __device__ __forceinline__ ull fma2(ull a, ull b, ull c) {
    ull d; asm("fma.rn.f32x2 %0, %1, %2, %3;" : "=l"(d) : "l"(a), "l"(b), "l"(c)); return d;
}
// HW tanh (sm_75+): 1 MUFU op
static __device__ __forceinline__ float tanha(float x) {
    float r; asm("tanh.approx.f32 %0, %1;" : "=f"(r) : "f"(x)); return r;
}
static __device__ __forceinline__ float ex2a(float x) {
    float r; asm("ex2.approx.f32 %0, %1;" : "=f"(r) : "f"(x)); return r;
}
#define LOG2E 1.4426950408889634f

#define BAR_SYNC(id)   asm volatile("bar.sync %0, 256;"   :: "r"(id) : "memory")
#define BAR_ARRIVE(id) asm volatile("bar.arrive %0, 256;" :: "r"(id) : "memory")

// W smem: [4 gates][64 k][64 n] = 64 KB  (LDS.64 lane-stride 8B -> 2 wavefronts, optimal)
// h smem: [2 buf][8 warps][4 batches][64 n] = 16 KB (per-warp private region)
#define WSM_FLOATS (4 * Nn * Nn)
#define HBUF (8 * 4 * Nn)
#define SMEM_BYTES ((WSM_FLOATS + 2 * HBUF) * 4)

__global__ void __launch_bounds__(256, 1)
imv_lstm_kernel(const float* __restrict__ x,
                const float* __restrict__ Uj, const float* __restrict__ Ui,
                const float* __restrict__ Uf, const float* __restrict__ Uo,
                const float* __restrict__ Wj, const float* __restrict__ Wi,
                const float* __restrict__ Wf, const float* __restrict__ Wo,
                const float* __restrict__ bj, const float* __restrict__ bi,
                const float* __restrict__ bf, const float* __restrict__ bo,
                const float* __restrict__ Fa, const float* __restrict__ Fab,
                const float* __restrict__ Fbw, const float* __restrict__ Fbb,
                const float* __restrict__ Phiw, const float* __restrict__ Phib)
{
    extern __shared__ float sm[];
    float* Wsm = sm;                 // [4][64][64]
    float* hsm = sm + WSM_FLOATS;    // h double buffer, per-warp regions

    const int tid = threadIdx.x;
    const int np  = tid & 31;        // n-pair index: n = {2np, 2np+1}
    const int w   = tid >> 5;        // warp id 0..7 -> 4 batches each
    const int d   = blockIdx.x & 31;
    const int bq  = blockIdx.x >> 5; // batch quarter 0..3
    const int b0  = bq * 32 + w * 4;
    const int n0  = 2 * np;
    const bool grpA = (w < 4);       // one warp of each group per SMSP (w&3 = SMSP id)

    // --- stage W[d] (4 gates) into smem [g][k][n]; sigmoid gates pre-halved ---
    {
        const float* Wg[4] = { Wj + d * Nn * Nn, Wi + d * Nn * Nn,
                               Wf + d * Nn * Nn, Wo + d * Nn * Nn };
#pragma unroll
        for (int g = 0; g < 4; g++) {
            const float scale = (g == 0) ? 1.f : 0.5f;   // sigmoid gates: tanh(z/2) form
            const float4* src = reinterpret_cast<const float4*>(Wg[g]);
            float4* dst = reinterpret_cast<float4*>(Wsm + g * Nn * Nn);
            for (int i = tid; i < (Nn * Nn) / 4; i += 256) {
                float4 v = src[i];
                v.x *= scale; v.y *= scale; v.z *= scale; v.w *= scale;
                dst[i] = v;
            }
        }
        for (int i = tid; i < 2 * HBUF; i += 256) hsm[i] = 0.f;
    }

    // --- per-thread constants (n0, n0+1 of this d); sigmoid gate U,b pre-halved ---
    const int dn = d * Nn + n0;
    const float ujx = Uj[dn],        ujy = Uj[dn + 1];
    const float uix = 0.5f*Ui[dn],   uiy = 0.5f*Ui[dn + 1];
    const float ufx = 0.5f*Uf[dn],   ufy = 0.5f*Uf[dn + 1];
    const float uox = 0.5f*Uo[dn],   uoy = 0.5f*Uo[dn + 1];
    const float bjx = bj[dn],        bjy = bj[dn + 1];
    const float bix = 0.5f*bi[dn],   biy = 0.5f*bi[dn + 1];
    const float bfx = 0.5f*bf[dn],   bfy = 0.5f*bf[dn + 1];
    const float box_ = 0.5f*bo[dn],  boy = 0.5f*bo[dn + 1];
    const float fax = Fa[dn],        fay = Fa[dn + 1];
    const float fab = Fab[d];

    // --- per-thread state: 4 batches x n-pair ---
    ull   c2[4]   = {0ull, 0ull, 0ull, 0ull};
    ull   h2[4]   = {0ull, 0ull, 0ull, 0ull};
    ull   gac2[4] = {0ull, 0ull, 0ull, 0ull};
    float suma[4] = {0.f, 0.f, 0.f, 0.f};

    __syncthreads();   // W + h staging visible to all warps

    const float* xb0 = x + b0 * (Tn * Dn) + d;
    float* hw = hsm + w * (4 * Nn);  // this warp's h region (buffer 0)

    int cur = 0;
    for (int t = 0; t < Tn; t++) {
        // enforced alternation: group B waits for group A's k-loop to finish,
        // so B's k-loop overlaps A's epilogue and vice versa (ping-pong).
        if (!grpA) BAR_SYNC(1);

        // prefetch x (latency hidden by the k-loop; consumed only in epilogue)
        float xv[4];
#pragma unroll
        for (int i = 0; i < 4; i++)
            xv[i] = __ldg(xb0 + i * (Tn * Dn) + t * Dn);

        ull aJ[4] = {0,0,0,0}, aI[4] = {0,0,0,0}, aF[4] = {0,0,0,0}, aO[4] = {0,0,0,0};

        const float* hb = hw + cur * HBUF;
#pragma unroll 2
        for (int k4 = 0; k4 < 16; k4++) {
            // broadcast float4 loads from this warp's own h region (warp-uniform addr)
            const float4 hv0 = *reinterpret_cast<const float4*>(hb + 0 * Nn + k4 * 4);
            const float4 hv1 = *reinterpret_cast<const float4*>(hb + 1 * Nn + k4 * 4);
            const float4 hv2 = *reinterpret_cast<const float4*>(hb + 2 * Nn + k4 * 4);
            const float4 hv3 = *reinterpret_cast<const float4*>(hb + 3 * Nn + k4 * 4);
            const float hvs[4][4] = {
                {hv0.x, hv1.x, hv2.x, hv3.x},
                {hv0.y, hv1.y, hv2.y, hv3.y},
                {hv0.z, hv1.z, hv2.z, hv3.z},
                {hv0.w, hv1.w, hv2.w, hv3.w}
            };
#pragma unroll
            for (int kk = 0; kk < 4; kk++) {
                const int k = k4 * 4 + kk;
                const float* wrow = Wsm + k * Nn + n0;   // lane-stride 8B -> 2 wavefronts
                const ull wjv = *reinterpret_cast<const ull*>(wrow);
                const ull wiv = *reinterpret_cast<const ull*>(wrow + Nn * Nn);
                const ull wfv = *reinterpret_cast<const ull*>(wrow + 2 * Nn * Nn);
                const ull wov = *reinterpret_cast<const ull*>(wrow + 3 * Nn * Nn);
                const ull h0 = pack2(hvs[kk][0], hvs[kk][0]);
                const ull h1 = pack2(hvs[kk][1], hvs[kk][1]);
                const ull hh2 = pack2(hvs[kk][2], hvs[kk][2]);
                const ull h3 = pack2(hvs[kk][3], hvs[kk][3]);
                aJ[0] = fma2(wjv, h0, aJ[0]); aJ[1] = fma2(wjv, h1, aJ[1]);
                aJ[2] = fma2(wjv, hh2, aJ[2]); aJ[3] = fma2(wjv, h3, aJ[3]);
                aI[0] = fma2(wiv, h0, aI[0]); aI[1] = fma2(wiv, h1, aI[1]);
                aI[2] = fma2(wiv, hh2, aI[2]); aI[3] = fma2(wiv, h3, aI[3]);
                aF[0] = fma2(wfv, h0, aF[0]); aF[1] = fma2(wfv, h1, aF[1]);
                aF[2] = fma2(wfv, hh2, aF[2]); aF[3] = fma2(wfv, h3, aF[3]);
                aO[0] = fma2(wov, h0, aO[0]); aO[1] = fma2(wov, h1, aO[1]);
                aO[2] = fma2(wov, hh2, aO[2]); aO[3] = fma2(wov, h3, aO[3]);
            }
        }

        // k-loop done: wake the other group
        if (grpA) BAR_ARRIVE(1); else BAR_ARRIVE(2);

        const int nxt = cur ^ 1;
        float pa[4];
        float* hwn = hw + nxt * HBUF;
#pragma unroll
        for (int i = 0; i < 4; i++) {
            float jx, jy, ix, iy, fx, fy, ox, oy;
            unpack2(aJ[i], jx, jy); unpack2(aI[i], ix, iy);
            unpack2(aF[i], fx, fy); unpack2(aO[i], ox, oy);
            const float xb = xv[i];
            // j gate: plain tanh
            jx = tanha(fmaf(xb, ujx, jx) + bjx);
            jy = tanha(fmaf(xb, ujy, jy) + bjy);
            // sigmoid gates: sigma(z) = 0.5*tanh(z/2)+0.5, W/U/b pre-halved
            ix = fmaf(0.5f, tanha(fmaf(xb, uix, ix) + bix), 0.5f);
            iy = fmaf(0.5f, tanha(fmaf(xb, uiy, iy) + biy), 0.5f);
            fx = fmaf(0.5f, tanha(fmaf(xb, ufx, fx) + bfx), 0.5f);
            fy = fmaf(0.5f, tanha(fmaf(xb, ufy, fy) + bfy), 0.5f);
            ox = fmaf(0.5f, tanha(fmaf(xb, uox, ox) + box_), 0.5f);
            oy = fmaf(0.5f, tanha(fmaf(xb, uoy, oy) + boy), 0.5f);
            float cx, cy; unpack2(c2[i], cx, cy);
            cx = fmaf(cx, fx, ix * jx);
            cy = fmaf(cy, fy, iy * jy);
            const float hx = ox * tanha(cx);
            const float hy = oy * tanha(cy);
            c2[i] = pack2(cx, cy);
            h2[i] = pack2(hx, hy);
            pa[i] = fmaf(hx, fax, hy * fay);
            // STS.64: own region, lane-stride 8B -> 2 wavefronts
            *reinterpret_cast<ull*>(hwn + i * Nn + n0) = h2[i];
        }
        __syncwarp();
        cur = nxt;

        // alpha accumulation
#pragma unroll
        for (int off = 16; off; off >>= 1) {
#pragma unroll
            for (int i = 0; i < 4; i++)
                pa[i] += __shfl_xor_sync(0xffffffffu, pa[i], off);
        }
#pragma unroll
        for (int i = 0; i < 4; i++) {
            const float a = ex2a(LOG2E * tanha(pa[i] + fab));
            suma[i] += a;
            gac2[i] = fma2(pack2(a, a), h2[i], gac2[i]);
        }

        // group A waits for group B's k-loop before starting its next k-loop
        if (grpA) BAR_SYNC(2);
    }

    // --- epilogue: g_n = gacc/suma, hg = [g_n, h_T], mu & beta dots ---
    float pm[4], pb[4];
    const float pwx  = Phiw[n0],      pwy  = Phiw[n0 + 1];
    const float pwx2 = Phiw[Nn + n0], pwy2 = Phiw[Nn + n0 + 1];
    const float fwx  = Fbw[n0],       fwy  = Fbw[n0 + 1];
    const float fwx2 = Fbw[Nn + n0],  fwy2 = Fbw[Nn + n0 + 1];
#pragma unroll
    for (int i = 0; i < 4; i++) {
        float gx, gy; unpack2(gac2[i], gx, gy);
        const float inv = __fdividef(1.f, suma[i]);
        gx *= inv; gy *= inv;
        float hx, hy; unpack2(h2[i], hx, hy);
        pm[i] = gx * pwx + gy * pwy + hx * pwx2 + hy * pwy2;
        pb[i] = gx * fwx + gy * fwy + hx * fwx2 + hy * fwy2;
    }
#pragma unroll
    for (int off = 16; off; off >>= 1) {
#pragma unroll
        for (int i = 0; i < 4; i++) {
            pm[i] += __shfl_xor_sync(0xffffffffu, pm[i], off);
            pb[i] += __shfl_xor_sync(0xffffffffu, pb[i], off);
        }
    }
    if (np == 0) {
        const float phib = Phib[0];
        const float fbb  = Fbb[0];
#pragma unroll
        for (int i = 0; i < 4; i++) {
            g_mu[(b0 + i) * Dn + d] = pm[i] + phib;
            g_tb[(b0 + i) * Dn + d] = ex2a(LOG2E * tanha(pb[i] + fbb));
        }
    }
}

__global__ void imv_finalize_kernel(float* __restrict__ out)
{
    const int b = threadIdx.x;
    float s = 0.f, acc = 0.f;
#pragma unroll
    for (int dd = 0; dd < Dn; dd++) {
        const float wgt = g_tb[b * Dn + dd];
        s   += wgt;
        acc += wgt * g_mu[b * Dn + dd];
    }
    out[b] = acc / s;
}

extern "C" void kernel_launch(void* const* d_in, const int* in_sizes, int n_in,
                              void* d_out, int out_size)
{
    (void)in_sizes; (void)n_in; (void)out_size;
    const float* x   = (const float*)d_in[0];
    const float* Uj  = (const float*)d_in[1];
    const float* Ui  = (const float*)d_in[2];
    const float* Uf  = (const float*)d_in[3];
    const float* Uo  = (const float*)d_in[4];
    const float* Wj  = (const float*)d_in[5];
    const float* Wi  = (const float*)d_in[6];
    const float* Wf  = (const float*)d_in[7];
    const float* Wo  = (const float*)d_in[8];
    const float* bj  = (const float*)d_in[9];
    const float* bi  = (const float*)d_in[10];
    const float* bf  = (const float*)d_in[11];
    const float* bo  = (const float*)d_in[12];
    const float* Fa  = (const float*)d_in[13];
    const float* Fab = (const float*)d_in[14];
    const float* Fbw = (const float*)d_in[15];
    const float* Fbb = (const float*)d_in[16];
    const float* Phw = (const float*)d_in[17];
    const float* Phb = (const float*)d_in[18];
    float* out = (float*)d_out;

    static int attr_set = 0;
    if (!attr_set) {
        cudaFuncSetAttribute(imv_lstm_kernel,
                             cudaFuncAttributeMaxDynamicSharedMemorySize,
                             SMEM_BYTES);
        attr_set = 1;
    }

    imv_lstm_kernel<<<Bn / 32 * Dn, 256, SMEM_BYTES>>>(
        x, Uj, Ui, Uf, Uo, Wj, Wi, Wf, Wo, bj, bi, bf, bo,
        Fa, Fab, Fbw, Fbb, Phw, Phb);
    imv_finalize_kernel<<<1, Bn>>>(out);
}

// round 11
// speedup vs baseline: 1.2786x; 1.2786x over previous
#include <cuda_runtime.h>

typedef unsigned long long ull;

#define Bn 128
#define Tn 512
#define Dn 32
#define Nn 64

// scratch for cross-d reduction (no allocations allowed)
__device__ float g_mu[Bn * Dn];
__device__ float g_tb[Bn * Dn];

static __device__ __forceinline__ ull pack2(float lo, float hi) {
    ull r; asm("mov.b64 %0, {%1, %2};" : "=l"(r) : "f"(lo), "f"(hi)); return r;
}
static __device__ __forceinline__ void unpack2(ull v, float &lo, float &hi) {
    asm("mov.b64 {%0, %1}, %2;" : "=f"(lo), "=f"(hi) : "l"(v));
}
// packed 2xfp32 FMA (Blackwell): d = a*b + c
static __device__ __forceinline__ ull fma2(ull a, ull b, ull c) {
    ull d; asm("fma.rn.f32x2 %0, %1, %2, %3;" : "=l"(d) : "l"(a), "l"(b), "l"(c)); return d;
}
// HW tanh (sm_75+): 1 MUFU op
static __device__ __forceinline__ float tanha(float x) {
    float r; asm("tanh.approx.f32 %0, %1;" : "=f"(r) : "f"(x)); return r;
}
static __device__ __forceinline__ float ex2a(float x) {
    float r; asm("ex2.approx.f32 %0, %1;" : "=f"(r) : "f"(x)); return r;
}
#define LOG2E 1.4426950408889634f

// W smem: [4 gates][32 kp][32 np][2 e][2 j] = 64 KB
//   one LDS.128 per (gate, k-pair) gives {W[k0][n0],W[k0][n1],W[k1][n0],W[k1][n1]}
//   lane stride 16B -> 4 conflict-free wavefronts
// h smem: [2 buf][8 warps][4 batches][64 n] = 16 KB (per-warp private region)
#define WSM_FLOATS (4 * Nn * Nn)
#define HBUF (8 * 4 * Nn)
#define SMEM_BYTES ((WSM_FLOATS + 2 * HBUF) * 4)

__global__ void __launch_bounds__(256, 1)
imv_lstm_kernel(const float* __restrict__ x,
                const float* __restrict__ Uj, const float* __restrict__ Ui,
                const float* __restrict__ Uf, const float* __restrict__ Uo,
                const float* __restrict__ Wj, const float* __restrict__ Wi,
                const float* __restrict__ Wf, const float* __restrict__ Wo,
                const float* __restrict__ bj, const float* __restrict__ bi,
                const float* __restrict__ bf, const float* __restrict__ bo,
                const float* __restrict__ Fa, const float* __restrict__ Fab,
                const float* __restrict__ Fbw, const float* __restrict__ Fbb,
                const float* __restrict__ Phiw, const float* __restrict__ Phib)
{
    extern __shared__ float sm[];
    float* Wsm = sm;                 // [4][32][32][2][2]
    float* hsm = sm + WSM_FLOATS;    // h double buffer, per-warp regions

    const int tid = threadIdx.x;
    const int np  = tid & 31;        // n-pair index: n = {2np, 2np+1}
    const int w   = tid >> 5;        // warp id 0..7 -> 4 batches each
    const int d   = blockIdx.x & 31;
    const int bq  = blockIdx.x >> 5; // batch quarter 0..3
    const int b0  = bq * 32 + w * 4;
    const int n0  = 2 * np;

    // --- stage W[d] into k-pair-packed smem; sigmoid gates pre-halved ---
    {
        const float* Wg[4] = { Wj + d * Nn * Nn, Wi + d * Nn * Nn,
                               Wf + d * Nn * Nn, Wo + d * Nn * Nn };
#pragma unroll
        for (int g = 0; g < 4; g++) {
            const float scale = (g == 0) ? 1.f : 0.5f;   // sigmoid gates: tanh(z/2) form
            const float* src = Wg[g];
            float* dst = Wsm + g * (Nn * Nn);
            for (int idx = tid; idx < Nn * Nn; idx += 256) {
                const int kp = idx >> 7;          // k-pair
                const int r  = idx & 127;
                const int p_ = r >> 2;            // n-pair
                const int e  = (r >> 1) & 1;      // k within pair
                const int jj = r & 1;             // n within pair
                dst[idx] = src[(2 * kp + e) * Nn + (2 * p_ + jj)] * scale;
            }
        }
        for (int i = tid; i < 2 * HBUF; i += 256) hsm[i] = 0.f;
    }

    // --- per-thread constants (n0, n0+1 of this d); sigmoid gate U,b pre-halved ---
    const int dn = d * Nn + n0;
    const float ujx = Uj[dn],        ujy = Uj[dn + 1];
    const float uix = 0.5f*Ui[dn],   uiy = 0.5f*Ui[dn + 1];
    const float ufx = 0.5f*Uf[dn],   ufy = 0.5f*Uf[dn + 1];
    const float uox = 0.5f*Uo[dn],   uoy = 0.5f*Uo[dn + 1];
    const float bjx = bj[dn],        bjy = bj[dn + 1];
    const float bix = 0.5f*bi[dn],   biy = 0.5f*bi[dn + 1];
    const float bfx = 0.5f*bf[dn],   bfy = 0.5f*bf[dn + 1];
    const float box_ = 0.5f*bo[dn],  boy = 0.5f*bo[dn + 1];
    const float fax = Fa[dn],        fay = Fa[dn + 1];
    const float fab = Fab[d];

    // --- per-thread state: 4 batches x n-pair ---
    ull   c2[4]   = {0ull, 0ull, 0ull, 0ull};
    ull   h2[4]   = {0ull, 0ull, 0ull, 0ull};
    ull   gac2[4] = {0ull, 0ull, 0ull, 0ull};
    float suma[4] = {0.f, 0.f, 0.f, 0.f};

    __syncthreads();   // W + h staging visible to all warps

    const float* xb0 = x + b0 * (Tn * Dn) + d;
    float* hw = hsm + w * (4 * Nn);  // this warp's h region (buffer 0)

    // per-lane W base pointers (float offset np*4 within each gate's k-pair row)
    const float* WJp = Wsm + 0 * (Nn * Nn) + np * 4;
    const float* WIp = Wsm + 1 * (Nn * Nn) + np * 4;
    const float* WFp = Wsm + 2 * (Nn * Nn) + np * 4;
    const float* WOp = Wsm + 3 * (Nn * Nn) + np * 4;

    int cur = 0;
    for (int t = 0; t < Tn; t++) {
        // prefetch x (latency hidden by the k-loop; consumed only in epilogue)
        float xv[4];
#pragma unroll
        for (int i = 0; i < 4; i++)
            xv[i] = __ldg(xb0 + i * (Tn * Dn) + t * Dn);

        ull aJ[4] = {0,0,0,0}, aI[4] = {0,0,0,0}, aF[4] = {0,0,0,0}, aO[4] = {0,0,0,0};

        const float* hb = hw + cur * HBUF;
#pragma unroll
        for (int k4 = 0; k4 < 16; k4++) {
            // broadcast float4 h loads (warp-uniform addr): 4 k for 4 batches
            const float4 hv0 = *reinterpret_cast<const float4*>(hb + 0 * Nn + k4 * 4);
            const float4 hv1 = *reinterpret_cast<const float4*>(hb + 1 * Nn + k4 * 4);
            const float4 hv2 = *reinterpret_cast<const float4*>(hb + 2 * Nn + k4 * 4);
            const float4 hv3 = *reinterpret_cast<const float4*>(hb + 3 * Nn + k4 * 4);
#pragma unroll
            for (int p = 0; p < 2; p++) {
                const int kpo = (2 * k4 + p) * 128;   // float offset of this k-pair row
                // one LDS.128 per gate: .x = k0 n-pair, .y = k1 n-pair
                const ulonglong2 wj = *reinterpret_cast<const ulonglong2*>(WJp + kpo);
                const ulonglong2 wi = *reinterpret_cast<const ulonglong2*>(WIp + kpo);
                const ulonglong2 wf = *reinterpret_cast<const ulonglong2*>(WFp + kpo);
                const ulonglong2 wo = *reinterpret_cast<const ulonglong2*>(WOp + kpo);
                const float h0a = p ? hv0.z : hv0.x, h0b = p ? hv0.w : hv0.y;
                const float h1a = p ? hv1.z : hv1.x, h1b = p ? hv1.w : hv1.y;
                const float h2a = p ? hv2.z : hv2.x, h2b = p ? hv2.w : hv2.y;
                const float h3a = p ? hv3.z : hv3.x, h3b = p ? hv3.w : hv3.y;
                const ull ha0 = pack2(h0a, h0a), hb0 = pack2(h0b, h0b);
                const ull ha1 = pack2(h1a, h1a), hb1 = pack2(h1b, h1b);
                const ull ha2 = pack2(h2a, h2a), hb2 = pack2(h2b, h2b);
                const ull ha3 = pack2(h3a, h3a), hb3 = pack2(h3b, h3b);
                aJ[0] = fma2(wj.x, ha0, aJ[0]); aJ[0] = fma2(wj.y, hb0, aJ[0]);
                aJ[1] = fma2(wj.x, ha1, aJ[1]); aJ[1] = fma2(wj.y, hb1, aJ[1]);
                aJ[2] = fma2(wj.x, ha2, aJ[2]); aJ[2] = fma2(wj.y, hb2, aJ[2]);
                aJ[3] = fma2(wj.x, ha3, aJ[3]); aJ[3] = fma2(wj.y, hb3, aJ[3]);
                aI[0] = fma2(wi.x, ha0, aI[0]); aI[0] = fma2(wi.y, hb0, aI[0]);
                aI[1] = fma2(wi.x, ha1, aI[1]); aI[1] = fma2(wi.y, hb1, aI[1]);
                aI[2] = fma2(wi.x, ha2, aI[2]); aI[2] = fma2(wi.y, hb2, aI[2]);
                aI[3] = fma2(wi.x, ha3, aI[3]); aI[3] = fma2(wi.y, hb3, aI[3]);
                aF[0] = fma2(wf.x, ha0, aF[0]); aF[0] = fma2(wf.y, hb0, aF[0]);
                aF[1] = fma2(wf.x, ha1, aF[1]); aF[1] = fma2(wf.y, hb1, aF[1]);
                aF[2] = fma2(wf.x, ha2, aF[2]); aF[2] = fma2(wf.y, hb2, aF[2]);
                aF[3] = fma2(wf.x, ha3, aF[3]); aF[3] = fma2(wf.y, hb3, aF[3]);
                aO[0] = fma2(wo.x, ha0, aO[0]); aO[0] = fma2(wo.y, hb0, aO[0]);
                aO[1] = fma2(wo.x, ha1, aO[1]); aO[1] = fma2(wo.y, hb1, aO[1]);
                aO[2] = fma2(wo.x, ha2, aO[2]); aO[2] = fma2(wo.y, hb2, aO[2]);
                aO[3] = fma2(wo.x, ha3, aO[3]); aO[3] = fma2(wo.y, hb3, aO[3]);
            }
        }

        const int nxt = cur ^ 1;
        float pa[4];
        float* hwn = hw + nxt * HBUF;
#pragma unroll
        for (int i = 0; i < 4; i++) {
            float jx, jy, ix, iy, fx, fy, ox, oy;
            unpack2(aJ[i], jx, jy); unpack2(aI[i], ix, iy);
            unpack2(aF[i], fx, fy); unpack2(aO[i], ox, oy);
            const float xb = xv[i];
            // j gate: plain tanh
            jx = tanha(fmaf(xb, ujx, jx) + bjx);
            jy = tanha(fmaf(xb, ujy, jy) + bjy);
            // sigmoid gates: sigma(z) = 0.5*tanh(z/2)+0.5, W/U/b pre-halved
            ix = fmaf(0.5f, tanha(fmaf(xb, uix, ix) + bix), 0.5f);
            iy = fmaf(0.5f, tanha(fmaf(xb, uiy, iy) + biy), 0.5f);
            fx = fmaf(0.5f, tanha(fmaf(xb, ufx, fx) + bfx), 0.5f);
            fy = fmaf(0.5f, tanha(fmaf(xb, ufy, fy) + bfy), 0.5f);
            ox = fmaf(0.5f, tanha(fmaf(xb, uox, ox) + box_), 0.5f);
            oy = fmaf(0.5f, tanha(fmaf(xb, uoy, oy) + boy), 0.5f);
            float cx, cy; unpack2(c2[i], cx, cy);
            cx = fmaf(cx, fx, ix * jx);
            cy = fmaf(cy, fy, iy * jy);
            const float hx = ox * tanha(cx);
            const float hy = oy * tanha(cy);
            c2[i] = pack2(cx, cy);
            h2[i] = pack2(hx, hy);
            pa[i] = fmaf(hx, fax, hy * fay);
            // STS.64: own region, lane-stride 8B -> 2 wavefronts
            *reinterpret_cast<ull*>(hwn + i * Nn + n0) = h2[i];
        }
        __syncwarp();
        cur = nxt;

        // alpha accumulation
#pragma unroll
        for (int off = 16; off; off >>= 1) {
#pragma unroll
            for (int i = 0; i < 4; i++)
                pa[i] += __shfl_xor_sync(0xffffffffu, pa[i], off);
        }
#pragma unroll
        for (int i = 0; i < 4; i++) {
            const float a = ex2a(LOG2E * tanha(pa[i] + fab));
            suma[i] += a;
            gac2[i] = fma2(pack2(a, a), h2[i], gac2[i]);
        }
    }

    // --- epilogue: g_n = gacc/suma, hg = [g_n, h_T], mu & beta dots ---
    float pm[4], pb[4];
    const float pwx  = Phiw[n0],      pwy  = Phiw[n0 + 1];
    const float pwx2 = Phiw[Nn + n0], pwy2 = Phiw[Nn + n0 + 1];
    const float fwx  = Fbw[n0],       fwy  = Fbw[n0 + 1];
    const float fwx2 = Fbw[Nn + n0],  fwy2 = Fbw[Nn + n0 + 1];
#pragma unroll
    for (int i = 0; i < 4; i++) {
        float gx, gy; unpack2(gac2[i], gx, gy);
        const float inv = __fdividef(1.f, suma[i]);
        gx *= inv; gy *= inv;
        float hx, hy; unpack2(h2[i], hx, hy);
        pm[i] = gx * pwx + gy * pwy + hx * pwx2 + hy * pwy2;
        pb[i] = gx * fwx + gy * fwy + hx * fwx2 + hy * fwy2;
    }
#pragma unroll
    for (int off = 16; off; off >>= 1) {
#pragma unroll
        for (int i = 0; i < 4; i++) {
            pm[i] += __shfl_xor_sync(0xffffffffu, pm[i], off);
            pb[i] += __shfl_xor_sync(0xffffffffu, pb[i], off);
        }
    }
    if (np == 0) {
        const float phib = Phib[0];
        const float fbb  = Fbb[0];
#pragma unroll
        for (int i = 0; i < 4; i++) {
            g_mu[(b0 + i) * Dn + d] = pm[i] + phib;
            g_tb[(b0 + i) * Dn + d] = ex2a(LOG2E * tanha(pb[i] + fbb));
        }
    }
}

__global__ void imv_finalize_kernel(float* __restrict__ out)
{
    const int b = threadIdx.x;
    float s = 0.f, acc = 0.f;
#pragma unroll
    for (int dd = 0; dd < Dn; dd++) {
        const float wgt = g_tb[b * Dn + dd];
        s   += wgt;
        acc += wgt * g_mu[b * Dn + dd];
    }
    out[b] = acc / s;
}

extern "C" void kernel_launch(void* const* d_in, const int* in_sizes, int n_in,
                              void* d_out, int out_size)
{
    (void)in_sizes; (void)n_in; (void)out_size;
    const float* x   = (const float*)d_in[0];
    const float* Uj  = (const float*)d_in[1];
    const float* Ui  = (const float*)d_in[2];
    const float* Uf  = (const float*)d_in[3];
    const float* Uo  = (const float*)d_in[4];
    const float* Wj  = (const float*)d_in[5];
    const float* Wi  = (const float*)d_in[6];
    const float* Wf  = (const float*)d_in[7];
    const float* Wo  = (const float*)d_in[8];
    const float* bj  = (const float*)d_in[9];
    const float* bi  = (const float*)d_in[10];
    const float* bf  = (const float*)d_in[11];
    const float* bo  = (const float*)d_in[12];
    const float* Fa  = (const float*)d_in[13];
    const float* Fab = (const float*)d_in[14];
    const float* Fbw = (const float*)d_in[15];
    const float* Fbb = (const float*)d_in[16];
    const float* Phw = (const float*)d_in[17];
    const float* Phb = (const float*)d_in[18];
    float* out = (float*)d_out;

    static int attr_set = 0;
    if (!attr_set) {
        cudaFuncSetAttribute(imv_lstm_kernel,
                             cudaFuncAttributeMaxDynamicSharedMemorySize,
                             SMEM_BYTES);
        attr_set = 1;
    }

    imv_lstm_kernel<<<Bn / 32 * Dn, 256, SMEM_BYTES>>>(
        x, Uj, Ui, Uf, Uo, Wj, Wi, Wf, Wo, bj, bi, bf, bo,
        Fa, Fab, Fbw, Fbb, Phw, Phb);
    imv_finalize_kernel<<<1, Bn>>>(out);
}